// round 10
// baseline (speedup 1.0000x reference)
#include <cuda_runtime.h>

// out[c] = sum_{i,j} w[i,j,c] * inputs[0,i,j,c];  H=W=512, C=256 (batch 0 only).
// 512 MB streaming read, HBM-bound. 4-slot modulo-scheduled LDG register ring,
// 40 warps/SM (occ 5), persistent single-wave grid.

#define THREADS 256
#define GRID    740                 // 148 SMs x 5 blocks, single wave
#define NF4     16777216            // 512*512*256 / 4 float4 per stream
#define STRIDE  (GRID * THREADS)    // f4 stride between a block's units: 189440

__global__ void zero_out_kernel(float* out) { out[threadIdx.x] = 0.0f; }

__global__ __launch_bounds__(THREADS, 5)
void chan_dot_ring(const float4* __restrict__ in,
                   const float4* __restrict__ w,
                   float* __restrict__ out)
{
    const int tid = threadIdx.x;
    const int tx  = tid & 63;     // channel quad
    const int ty  = tid >> 6;

    // Unit u (0..65535) covers f4 range [u*256, u*256+256); this thread owns
    // element u*256 + tid  (channel quad == tid & 63). Block b owns units
    // b, b+GRID, b+2*GRID, ...  -> gi advances by STRIDE.
    const float4 z4 = make_float4(0.f, 0.f, 0.f, 0.f);
    float4 a0 = z4, a1 = z4, a2 = z4, a3 = z4;
    float4 b0 = z4, b1 = z4, b2 = z4, b3 = z4;
    float ax = 0.f, ay = 0.f, az = 0.f, aw = 0.f;

#define LOADU(A, B)  do {                         \
        if (gi < NF4) {                           \
            A = __ldcs(in + gi);                  \
            B = __ldcs(w  + gi);                  \
        }                                         \
        gi += STRIDE;                             \
    } while (0)

#define FMAU(A, B)   do {                         \
        ax = fmaf(A.x, B.x, ax);                  \
        ay = fmaf(A.y, B.y, ay);                  \
        az = fmaf(A.z, B.z, az);                  \
        aw = fmaf(A.w, B.w, aw);                  \
    } while (0)

    int gi = blockIdx.x * THREADS + tid;          // f4 index of this thread's unit 0
    const int mine = (NF4 - 1 - (int)(blockIdx.x * THREADS + tid)) / STRIDE + 1; // units for this block

    // Prologue: preload slots 0..2 (mine >= 88, always valid)
    LOADU(a0, b0);
    LOADU(a1, b1);
    LOADU(a2, b2);

    // Steady state: load slot (k+3), FMA slot k. FMA waits on a load issued
    // 3 stages earlier; 3 batches (96 B/thread) perpetually in flight.
    int k = 0;
    for (; k + 4 <= mine; k += 4) {
        LOADU(a3, b3);  FMAU(a0, b0);
        LOADU(a0, b0);  FMAU(a1, b1);
        LOADU(a1, b1);  FMAU(a2, b2);
        LOADU(a2, b2);  FMAU(a3, b3);
    }
    // Epilogue: 0..3 remaining units sit in slots 0..2 (slot 3 load was guarded off)
    if (k     < mine) FMAU(a0, b0);
    if (k + 1 < mine) FMAU(a1, b1);
    if (k + 2 < mine) FMAU(a2, b2);

#undef LOADU
#undef FMAU

    // Block reduction over the 4 ty-lanes per channel quad, then atomics.
    __shared__ float4 red[4][64];
    red[ty][tx] = make_float4(ax, ay, az, aw);
    __syncthreads();
    if (ty == 0) {
        const float4 t0 = red[0][tx];
        const float4 t1 = red[1][tx];
        const float4 t2 = red[2][tx];
        const float4 t3 = red[3][tx];
        atomicAdd(&out[tx * 4 + 0], (t0.x + t1.x) + (t2.x + t3.x));
        atomicAdd(&out[tx * 4 + 1], (t0.y + t1.y) + (t2.y + t3.y));
        atomicAdd(&out[tx * 4 + 2], (t0.z + t1.z) + (t2.z + t3.z));
        atomicAdd(&out[tx * 4 + 3], (t0.w + t1.w) + (t2.w + t3.w));
    }
}

extern "C" void kernel_launch(void* const* d_in, const int* in_sizes, int n_in,
                              void* d_out, int out_size) {
    const float4* in = (const float4*)d_in[0];   // (2,512,512,256) f32; batch 0 only
    const float4* w  = (const float4*)d_in[1];   // (512,512,256) f32
    float* out = (float*)d_out;                  // 256 f32

    zero_out_kernel<<<1, 256>>>(out);
    chan_dot_ring<<<GRID, THREADS>>>(in, w, out);
}

// round 12
// speedup vs baseline: 1.2538x; 1.2538x over previous
#include <cuda_runtime.h>

// out[c] = sum_{i,j} w[i,j,c] * inputs[0,i,j,c];  H=W=512, C=256 (batch 0 only).
// R4 structure (best measured: 95.4us, DRAM 71%) + L2 software prefetch PF=3
// iterations ahead: deepens DRAM-level MLP without spending registers.

#define NPOS   (512 * 512)
#define GRID   592                 // 148 SMs x 4 blocks: exactly one wave
#define UNITS  (NPOS / 8)          // work unit = 8 positions; 32768 units
#define NF4    16777216            // f4 elements per stream
#define PF     3                   // prefetch distance in units-of-GRID

__global__ void zero_out_kernel(float* out) { out[threadIdx.x] = 0.0f; }

__device__ __forceinline__ void pf_l2(const float4* p) {
    asm volatile("prefetch.global.L2 [%0];" :: "l"(p));
}

__global__ __launch_bounds__(256, 4)
void chan_dot_kernel(const float4* __restrict__ in,
                     const float4* __restrict__ w,
                     float* __restrict__ out) {
    const int tx = threadIdx.x & 63;   // channel quad
    const int ty = threadIdx.x >> 6;   // 0..3 position sub-lane

    float ax = 0.f, ay = 0.f, az = 0.f, aw = 0.f;

    float4 a0[2], b0[2], a1[2], b1[2];

    // Unit u covers positions [8u, 8u+8); thread handles positions 8u+2*ty+{0,1}.
    // Warp reads 512B contiguous per position per stream -> fully coalesced.
    // After the 4 blocking LDGs, prefetch unit u+PF*GRID into L2 (no regs, no SB).
#define LOADB(A, B, u) do {                               \
        const int _base = ((u) * 8 + ty * 2) * 64 + tx;   \
        A[0] = __ldcs(in + _base);                        \
        A[1] = __ldcs(in + _base + 64);                   \
        B[0] = __ldcs(w  + _base);                        \
        B[1] = __ldcs(w  + _base + 64);                   \
        const int _pfi = _base + PF * GRID * 512;         \
        if (_pfi + 64 < NF4) {                            \
            pf_l2(in + _pfi);                             \
            pf_l2(in + _pfi + 64);                        \
            pf_l2(w  + _pfi);                             \
            pf_l2(w  + _pfi + 64);                        \
        }                                                 \
    } while (0)

#define FMAB(A, B) do {                                   \
        ax = fmaf(A[0].x, B[0].x, ax);                    \
        ay = fmaf(A[0].y, B[0].y, ay);                    \
        az = fmaf(A[0].z, B[0].z, az);                    \
        aw = fmaf(A[0].w, B[0].w, aw);                    \
        ax = fmaf(A[1].x, B[1].x, ax);                    \
        ay = fmaf(A[1].y, B[1].y, ay);                    \
        az = fmaf(A[1].z, B[1].z, az);                    \
        aw = fmaf(A[1].w, B[1].w, aw);                    \
    } while (0)

    int u = blockIdx.x;                 // < GRID <= UNITS, initial load always valid
    LOADB(a0, b0, u);
    for (;;) {
        const int u1 = u + GRID;
        if (u1 < UNITS) LOADB(a1, b1, u1);   // next batch in flight during these FMAs
        FMAB(a0, b0);
        if (u1 >= UNITS) break;

        const int u2 = u1 + GRID;
        if (u2 < UNITS) LOADB(a0, b0, u2);
        FMAB(a1, b1);
        if (u2 >= UNITS) break;
        u = u2;
    }

    // Reduce 4 position sub-lanes per channel quad via smem, then atomics.
    __shared__ float4 s[4][64];
    s[ty][tx] = make_float4(ax, ay, az, aw);
    __syncthreads();

    if (ty == 0) {
        const float4 t0 = s[0][tx];
        const float4 t1 = s[1][tx];
        const float4 t2 = s[2][tx];
        const float4 t3 = s[3][tx];
        atomicAdd(&out[tx * 4 + 0], (t0.x + t1.x) + (t2.x + t3.x));
        atomicAdd(&out[tx * 4 + 1], (t0.y + t1.y) + (t2.y + t3.y));
        atomicAdd(&out[tx * 4 + 2], (t0.z + t1.z) + (t2.z + t3.z));
        atomicAdd(&out[tx * 4 + 3], (t0.w + t1.w) + (t2.w + t3.w));
    }
}

extern "C" void kernel_launch(void* const* d_in, const int* in_sizes, int n_in,
                              void* d_out, int out_size) {
    const float4* in = (const float4*)d_in[0];   // (2,512,512,256) f32; batch 0 only
    const float4* w  = (const float4*)d_in[1];   // (512,512,256) f32
    float* out = (float*)d_out;                  // 256 f32

    zero_out_kernel<<<1, 256>>>(out);
    chan_dot_kernel<<<GRID, 256>>>(in, w, out);
}